// round 1
// baseline (speedup 1.0000x reference)
#include <cuda_runtime.h>

// ---------------- configuration ----------------
#define TN   128          // nodes per tile
#define SP   130          // activation buffer row stride (floats), even for f32x2
#define KC   32           // k-chunk staged from gmem for big GEMMs

// ---------------- shared memory layout (float offsets) ----------------
#define A256_OFF  0
#define A256_SZ   (256 * SP)                 // 33280
#define A128_OFF  (A256_OFF + A256_SZ)
#define A128_SZ   (128 * SP)                 // 16640
#define STAGE_OFF (A128_OFF + A128_SZ)
#define STAGE_SZ  (KC * 128)                 // 4096
#define CON_OFF   (STAGE_OFF + STAGE_SZ)
#define C_B1      (CON_OFF)                  // 256
#define C_BE1     (C_B1 + 256)               // 128
#define C_WE2     (C_BE1 + 128)              // 768  (128x6)
#define C_BE2     (C_WE2 + 768)              // 8    (6 used)
#define C_WD1     (C_BE2 + 8)                // 768  (6x128)
#define C_BD1     (C_WD1 + 768)              // 128
#define C_BD2     (C_BD1 + 128)              // 256
#define C_WO      (C_BD2 + 256)              // 256
#define C_BO      (C_WO + 256)               // 4
#define SMEM_FLOATS (C_BO + 4)
#define SMEM_BYTES  (SMEM_FLOATS * 4)        // 226,352 B  (<= 232,448 opt-in)

// msgs buffer aliases A128 region ([16][SP]); z aliases A256 region ([6][SP]);
// O-layer scratch aliases STAGE region.

typedef unsigned long long u64t;

__device__ __forceinline__ u64t pack2(float lo, float hi) {
    u64t r; asm("mov.b64 %0, {%1, %2};" : "=l"(r) : "f"(lo), "f"(hi)); return r;
}
__device__ __forceinline__ void unpack2(u64t v, float& lo, float& hi) {
    asm("mov.b64 {%0, %1}, %2;" : "=f"(lo), "=f"(hi) : "l"(v));
}
__device__ __forceinline__ void fma2(u64t& d, u64t a, u64t b) {
    // packed fp32x2 FMA: 2 MACs/lane/instr -> 128 MAC/SM/cyc (vs 64 for FFMA-3reg)
    asm("fma.rn.f32x2 %0, %1, %2, %0;" : "+l"(d) : "l"(a), "l"(b));
}
__device__ __forceinline__ float tanh_fast(float x) {
    float xa = fminf(fmaxf(x, -9.f), 9.f);
    float e  = __expf(2.f * xa);
    return __fdividef(e - 1.f, e + 1.f);   // rel err ~1e-6, 2 MUFU ops
}

// ---------------- big GEMM: act(feature-major smem) @ W(gmem, staged) ----------------
// out[c][r] = (tanh?)( sum_k in[k][r] * W[k*ldw + coff + c] + bias[coff + c] )
// 16x16 thread grid; per-thread 8 rows (pairs) x 8 cols.
template<int K, bool DOTANH>
__device__ __forceinline__ void gemm_big(float* sm, int in_off,
                                         const float* __restrict__ W, int ldw, int coff,
                                         int bias_off, int out_off)
{
    const int tid = threadIdx.x;
    const int tx  = tid & 15, ty = tid >> 4;
    const int r0  = ty * 8;     // 8 consecutive rows per thread (f32x2 pairs)
    const int c0  = tx;         // cols c0 + 16*j

    u64t acc[4][8];
#pragma unroll
    for (int i = 0; i < 4; ++i)
#pragma unroll
        for (int j = 0; j < 8; ++j) acc[i][j] = 0ull;

    for (int k0 = 0; k0 < K; k0 += KC) {
        __syncthreads();   // previous stage consumers done
        // stage W rows [k0, k0+KC) x 128 cols -> smem (4 float4 per thread)
#pragma unroll
        for (int q = 0; q < 4; ++q) {
            int idx4 = tid + q * 256;              // 0..1023
            int row  = idx4 >> 5;
            int c4   = (idx4 & 31) << 2;
            *(float4*)&sm[STAGE_OFF + row * 128 + c4] =
                *(const float4*)&W[(size_t)(k0 + row) * ldw + coff + c4];
        }
        __syncthreads();
#pragma unroll 4
        for (int kk = 0; kk < KC; ++kk) {
            const float* A = &sm[in_off + (k0 + kk) * SP + r0];
            u64t a0 = *(const u64t*)(A + 0);
            u64t a1 = *(const u64t*)(A + 2);
            u64t a2 = *(const u64t*)(A + 4);
            u64t a3 = *(const u64t*)(A + 6);
            const float* B = &sm[STAGE_OFF + kk * 128 + c0];
#pragma unroll
            for (int j = 0; j < 8; ++j) {
                float b = B[16 * j];
                u64t bb = pack2(b, b);
                fma2(acc[0][j], a0, bb);
                fma2(acc[1][j], a1, bb);
                fma2(acc[2][j], a2, bb);
                fma2(acc[3][j], a3, bb);
            }
        }
    }
    // epilogue: bias (+tanh) -> feature-major out buffer
#pragma unroll
    for (int j = 0; j < 8; ++j) {
        int c = coff + c0 + 16 * j;
        float bias = sm[bias_off + c];
#pragma unroll
        for (int i2 = 0; i2 < 4; ++i2) {
            float lo, hi; unpack2(acc[i2][j], lo, hi);
            lo += bias; hi += bias;
            if (DOTANH) { lo = tanh_fast(lo); hi = tanh_fast(hi); }
            sm[out_off + c * SP + r0 + 2 * i2]     = lo;
            sm[out_off + c * SP + r0 + 2 * i2 + 1] = hi;
        }
    }
}

// ---------------- L1: msgs(16) -> 256, tanh.  W1 read direct from L2. ----------------
__device__ __forceinline__ void layer_L1(float* sm, const float* __restrict__ W1)
{
    const int tid = threadIdx.x;
    const int tx  = tid & 15, ty = tid >> 4;
    const int r0  = ty * 8, c0 = tx;
#pragma unroll 1
    for (int cg = 0; cg < 2; ++cg) {
        u64t acc[4][8];
#pragma unroll
        for (int i = 0; i < 4; ++i)
#pragma unroll
            for (int j = 0; j < 8; ++j) acc[i][j] = 0ull;
#pragma unroll 4
        for (int k = 0; k < 16; ++k) {
            const float* A = &sm[A128_OFF + k * SP + r0];   // msgs alias
            u64t a0 = *(const u64t*)(A + 0);
            u64t a1 = *(const u64t*)(A + 2);
            u64t a2 = *(const u64t*)(A + 4);
            u64t a3 = *(const u64t*)(A + 6);
            const float* B = &W1[k * 256 + cg * 128 + c0];
#pragma unroll
            for (int j = 0; j < 8; ++j) {
                float b = __ldg(&B[16 * j]);
                u64t bb = pack2(b, b);
                fma2(acc[0][j], a0, bb);
                fma2(acc[1][j], a1, bb);
                fma2(acc[2][j], a2, bb);
                fma2(acc[3][j], a3, bb);
            }
        }
#pragma unroll
        for (int j = 0; j < 8; ++j) {
            int c = cg * 128 + c0 + 16 * j;
            float bias = sm[C_B1 + c];
#pragma unroll
            for (int i2 = 0; i2 < 4; ++i2) {
                float lo, hi; unpack2(acc[i2][j], lo, hi);
                sm[A256_OFF + c * SP + r0 + 2 * i2]     = tanh_fast(lo + bias);
                sm[A256_OFF + c * SP + r0 + 2 * i2 + 1] = tanh_fast(hi + bias);
            }
        }
    }
}

// ---------------- E2: 128 -> 6, tanh.  z written to A256 region. ----------------
__device__ __forceinline__ void layer_E2(float* sm)
{
    const int tid = threadIdx.x;
    const int r  = tid & 127;
    const int jg = tid >> 7;          // 0 or 1 -> outputs 3*jg .. 3*jg+2
    float a0 = 0.f, a1 = 0.f, a2 = 0.f;
#pragma unroll 8
    for (int k = 0; k < 128; ++k) {
        float a = sm[A128_OFF + k * SP + r];
        const float* w = &sm[C_WE2 + k * 6 + jg * 3];
        a0 = fmaf(a, w[0], a0);
        a1 = fmaf(a, w[1], a1);
        a2 = fmaf(a, w[2], a2);
    }
    const float* be = &sm[C_BE2 + jg * 3];
    sm[A256_OFF + (jg * 3 + 0) * SP + r] = tanh_fast(a0 + be[0]);
    sm[A256_OFF + (jg * 3 + 1) * SP + r] = tanh_fast(a1 + be[1]);
    sm[A256_OFF + (jg * 3 + 2) * SP + r] = tanh_fast(a2 + be[2]);
}

// ---------------- D1: 6 -> 128, tanh ----------------
__device__ __forceinline__ void layer_D1(float* sm)
{
    const int tid = threadIdx.x;
    const int tx  = tid & 15, ty = tid >> 4;
    const int r0  = ty * 8, c0 = tx;
    u64t acc[4][8];
#pragma unroll
    for (int i = 0; i < 4; ++i)
#pragma unroll
        for (int j = 0; j < 8; ++j) acc[i][j] = 0ull;
#pragma unroll
    for (int k = 0; k < 6; ++k) {
        const float* A = &sm[A256_OFF + k * SP + r0];       // z alias
        u64t a0 = *(const u64t*)(A + 0);
        u64t a1 = *(const u64t*)(A + 2);
        u64t a2 = *(const u64t*)(A + 4);
        u64t a3 = *(const u64t*)(A + 6);
        const float* B = &sm[C_WD1 + k * 128 + c0];
#pragma unroll
        for (int j = 0; j < 8; ++j) {
            float b = B[16 * j];
            u64t bb = pack2(b, b);
            fma2(acc[0][j], a0, bb);
            fma2(acc[1][j], a1, bb);
            fma2(acc[2][j], a2, bb);
            fma2(acc[3][j], a3, bb);
        }
    }
#pragma unroll
    for (int j = 0; j < 8; ++j) {
        int c = c0 + 16 * j;
        float bias = sm[C_BD1 + c];
#pragma unroll
        for (int i2 = 0; i2 < 4; ++i2) {
            float lo, hi; unpack2(acc[i2][j], lo, hi);
            sm[A128_OFF + c * SP + r0 + 2 * i2]     = tanh_fast(lo + bias);
            sm[A128_OFF + c * SP + r0 + 2 * i2 + 1] = tanh_fast(hi + bias);
        }
    }
}

// ---------------- O: out = sigmoid(tanh(d) @ Wo + bo) ----------------
__device__ __forceinline__ void layer_O(float* sm, float* __restrict__ out, int nb, int Nn)
{
    const int tid = threadIdx.x;
    const int r   = tid & 127;
    const int kh  = tid >> 7;         // k half: 0 or 1
    float p = 0.f;
#pragma unroll 8
    for (int kk = 0; kk < 128; ++kk) {
        int k = (kh << 7) + kk;
        p = fmaf(tanh_fast(sm[A256_OFF + k * SP + r]), sm[C_WO + k], p);
    }
    if (kh) sm[STAGE_OFF + r] = p;    // scratch aliases stage buffer
    __syncthreads();
    if (!kh) {
        float tot = p + sm[STAGE_OFF + r] + sm[C_BO];
        float sig = __fdividef(1.f, 1.f + __expf(-tot));
        int node = nb + r;
        if (node < Nn) out[node] = sig;
    }
}

// ---------------- main fused kernel ----------------
__global__ void __launch_bounds__(256, 1)
gnn_fused_kernel(const float* __restrict__ edge_attr,
                 const float* __restrict__ W1,  const float* __restrict__ b1,
                 const float* __restrict__ We1, const float* __restrict__ be1,
                 const float* __restrict__ We2, const float* __restrict__ be2,
                 const float* __restrict__ Wd1, const float* __restrict__ bd1,
                 const float* __restrict__ Wd2, const float* __restrict__ bd2,
                 const float* __restrict__ Wo,  const float* __restrict__ bo,
                 float* __restrict__ out, int Nn, int ntiles)
{
    extern __shared__ float sm[];
    const int tid = threadIdx.x;

    // cache small constants once per block
    if (tid < 256) sm[C_B1  + tid] = b1[tid];
    if (tid < 128) sm[C_BE1 + tid] = be1[tid];
    for (int i = tid; i < 768; i += 256) sm[C_WE2 + i] = We2[i];
    if (tid < 6)   sm[C_BE2 + tid] = be2[tid];
    for (int i = tid; i < 768; i += 256) sm[C_WD1 + i] = Wd1[i];
    if (tid < 128) sm[C_BD1 + tid] = bd1[tid];
    if (tid < 256) sm[C_BD2 + tid] = bd2[tid];
    if (tid < 256) sm[C_WO  + tid] = Wo[tid];
    if (tid == 0)  sm[C_BO] = bo[0];

    for (int tile = blockIdx.x; tile < ntiles; tile += gridDim.x) {
        const int nb = tile * TN;
        __syncthreads();   // buffers from previous tile fully consumed

        // load msgs tile (TN x 16, contiguous) -> transposed [16][SP] at A128 region
#pragma unroll
        for (int q = 0; q < 2; ++q) {
            int idx4 = tid + q * 256;         // 512 float4s = 2048 floats
            int lin  = idx4 << 2;
            int node = lin >> 4;
            int k    = lin & 15;
            float4 v = make_float4(0.f, 0.f, 0.f, 0.f);
            if (nb + node < Nn)
                v = *(const float4*)&edge_attr[(size_t)(nb + node) * 16 + k];
            sm[A128_OFF + (k + 0) * SP + node] = v.x;
            sm[A128_OFF + (k + 1) * SP + node] = v.y;
            sm[A128_OFF + (k + 2) * SP + node] = v.z;
            sm[A128_OFF + (k + 3) * SP + node] = v.w;
        }
        __syncthreads();

        layer_L1(sm, W1);                                            // msgs -> A256 (tanh)
        __syncthreads();
        gemm_big<256, true>(sm, A256_OFF, We1, 128, 0,   C_BE1, A128_OFF);  // E1 -> A128 (tanh)
        __syncthreads();
        layer_E2(sm);                                                // A128 -> z (A256 region)
        __syncthreads();
        layer_D1(sm);                                                // z -> A128 (tanh)
        __syncthreads();
        gemm_big<128, false>(sm, A128_OFF, Wd2, 256, 0,   C_BD2, A256_OFF); // D2 lo -> A256
        gemm_big<128, false>(sm, A128_OFF, Wd2, 256, 128, C_BD2, A256_OFF); // D2 hi -> A256
        __syncthreads();
        layer_O(sm, out, nb, Nn);                                    // A256 -> gmem
    }
}

// ---------------- launch ----------------
extern "C" void kernel_launch(void* const* d_in, const int* in_sizes, int n_in,
                              void* d_out, int out_size)
{
    // metadata order: x, edge_index, edge_attr, W1, b1, We1, be1, We2, be2,
    //                 Wd1, bd1, Wd2, bd2, Wo, bo   (x/edge_index unused)
    const float* edge_attr = (const float*)d_in[2];
    const float* W1  = (const float*)d_in[3];
    const float* b1  = (const float*)d_in[4];
    const float* We1 = (const float*)d_in[5];
    const float* be1 = (const float*)d_in[6];
    const float* We2 = (const float*)d_in[7];
    const float* be2 = (const float*)d_in[8];
    const float* Wd1 = (const float*)d_in[9];
    const float* bd1 = (const float*)d_in[10];
    const float* Wd2 = (const float*)d_in[11];
    const float* bd2 = (const float*)d_in[12];
    const float* Wo  = (const float*)d_in[13];
    const float* bo  = (const float*)d_in[14];
    float* out = (float*)d_out;

    const int Nn = out_size;
    const int ntiles = (Nn + TN - 1) / TN;

    cudaFuncSetAttribute(gnn_fused_kernel,
                         cudaFuncAttributeMaxDynamicSharedMemorySize, SMEM_BYTES);
    int sms = 148;
    cudaDeviceGetAttribute(&sms, cudaDevAttrMultiProcessorCount, 0);
    int grid = ntiles < sms ? ntiles : sms;

    gnn_fused_kernel<<<grid, 256, SMEM_BYTES>>>(
        edge_attr, W1, b1, We1, be1, We2, be2, Wd1, bd1, Wd2, bd2, Wo, bo,
        out, Nn, ntiles);
}